// round 11
// baseline (speedup 1.0000x reference)
#include <cuda_runtime.h>
#include <cstdint>

// Problem constants
static constexpr int B = 32;
static constexpr int L = 4096;
static constexpr int C = 8;
static constexpr int T = 64;
static constexpr long long NELEM = (long long)B * L * C;   // 1,048,576

static constexpr int RED_BLOCKS  = 512;
static constexpr int RED_THREADS = 128;
// 512*128 threads * 16 elems = 1,048,576 == NELEM exactly

// Deterministic scratch (fixed-slot partials)
__device__ double   g_psum[RED_BLOCKS];
__device__ double   g_psumsq[RED_BLOCKS];
__device__ float    g_mean;
__device__ float    g_inv;    // rsqrt.approx(var + eps)
__device__ unsigned g_count = 0;   // last-block-done counter (reset after use)

__device__ __forceinline__ float rsqrt_approx(float x) {
    float r;
    asm("rsqrt.approx.f32 %0, %1;" : "=f"(r) : "f"(x));
    return r;
}

// ---------------------------------------------------------------------------
// K1: partial sums of delta and delta^2 + fused last-block finalize.
// Same proven 16-elem/thread body (6 independent LDG.128), reshaped to
// 512 CTAs x 128 threads for CTA balance (3.46/SM vs 1.73).
// delta[idx] = in[idx] - in[idx-8] (stride C along l), 0 at l==0 (head
// chunk of each batch row zeroes its first 8 slots).
// ---------------------------------------------------------------------------
__global__ void __launch_bounds__(RED_THREADS) reduce_kernel(const float* __restrict__ in) {
    const int tid  = blockIdx.x * blockDim.x + threadIdx.x;
    const int base = tid * 16;
    const float* p = in + base;

    float4 v0, v1, v2, v3, v4, v5;
    v2 = *reinterpret_cast<const float4*>(p);
    v3 = *reinterpret_cast<const float4*>(p + 4);
    v4 = *reinterpret_cast<const float4*>(p + 8);
    v5 = *reinterpret_cast<const float4*>(p + 12);
    if (base == 0) {
        v0 = make_float4(0.f, 0.f, 0.f, 0.f);
        v1 = v0;
    } else {
        v0 = *reinterpret_cast<const float4*>(p - 8);
        v1 = *reinterpret_cast<const float4*>(p - 4);
    }

    float a[24] = { v0.x, v0.y, v0.z, v0.w,  v1.x, v1.y, v1.z, v1.w,
                    v2.x, v2.y, v2.z, v2.w,  v3.x, v3.y, v3.z, v3.w,
                    v4.x, v4.y, v4.z, v4.w,  v5.x, v5.y, v5.z, v5.w };

    const bool head = (base & (L * C - 1)) == 0;   // first 16-chunk of a batch row
    float s = 0.0f, q = 0.0f;
    #pragma unroll
    for (int j = 0; j < 16; ++j) {
        float delta = a[j + 8] - a[j];
        if (head && j < 8) delta = 0.0f;
        s += delta;
        q  = fmaf(delta, delta, q);
    }

    #pragma unroll
    for (int o = 16; o > 0; o >>= 1) {
        s += __shfl_down_sync(0xffffffffu, s, o);
        q += __shfl_down_sync(0xffffffffu, q, o);
    }

    __shared__ double ws[4], wq[4];
    const int t    = threadIdx.x;
    const int lane = t & 31;
    const int warp = t >> 5;     // 0..3
    if (lane == 0) { ws[warp] = (double)s; wq[warp] = (double)q; }
    __syncthreads();

    __shared__ bool isLast;
    if (warp == 0) {
        double ds = (lane < 4) ? ws[lane] : 0.0;
        double dq = (lane < 4) ? wq[lane] : 0.0;
        #pragma unroll
        for (int o = 2; o > 0; o >>= 1) {
            ds += __shfl_down_sync(0xffffffffu, ds, o);
            dq += __shfl_down_sync(0xffffffffu, dq, o);
        }
        if (lane == 0) {
            g_psum[blockIdx.x]   = ds;
            g_psumsq[blockIdx.x] = dq;
            __threadfence();
            unsigned prev = atomicAdd(&g_count, 1u);
            isLast = (prev == RED_BLOCKS - 1);
        }
    }
    __syncthreads();

    if (isLast) {
        __threadfence();   // acquire all blocks' partials
        double ds = g_psum[t]       + g_psum[t + 128]
                  + g_psum[t + 256] + g_psum[t + 384];
        double dq = g_psumsq[t]       + g_psumsq[t + 128]
                  + g_psumsq[t + 256] + g_psumsq[t + 384];
        #pragma unroll
        for (int o = 16; o > 0; o >>= 1) {
            ds += __shfl_down_sync(0xffffffffu, ds, o);
            dq += __shfl_down_sync(0xffffffffu, dq, o);
        }
        __shared__ double fs[4], fq[4];
        if (lane == 0) { fs[warp] = ds; fq[warp] = dq; }
        __syncthreads();
        if (t == 0) {
            double S = 0.0, Q = 0.0;
            #pragma unroll
            for (int w = 0; w < 4; ++w) { S += fs[w]; Q += fq[w]; }
            double mean = S / (double)NELEM;
            double var  = Q / (double)NELEM - mean * mean;
            g_mean  = (float)mean;
            g_inv   = rsqrt_approx((float)var + 1e-5f);
            g_count = 0;   // reset for next graph replay
        }
    }
}

// ---------------------------------------------------------------------------
// K3: main — normalize delta, encode across T=64, LIF recurrence, spike out.
// ILP x2 over R10: one thread = 16 l's for one (b, c) as FOUR disjoint
// 4-chunks at l0 + k*(L/4), k=0..3 -> 4 independent 512B-burst float4 .cs
// stores per t-iteration. 1024 CTAs x 64 threads keeps the balanced 6.92
// CTAs/SM that won in R10.
// out layout: [B, T, C, L] -> ((b*T + t)*C + c)*L + l
// ---------------------------------------------------------------------------
__global__ void __launch_bounds__(64) lif_kernel(
    const float* __restrict__ in,
    const float* __restrict__ enc_w,
    const float* __restrict__ enc_b,
    const float* __restrict__ bn_gamma,
    const float* __restrict__ bn_beta,
    float* __restrict__ out)
{
    __shared__ float sw[T];
    __shared__ float sb[T];
    if (threadIdx.x < T) {
        sw[threadIdx.x] = enc_w[threadIdx.x];   // enc_w is [T,1]
        sb[threadIdx.x] = enc_b[threadIdx.x];
    }
    __syncthreads();

    const int idx = blockIdx.x * blockDim.x + threadIdx.x;  // 0 .. 65535
    const int lv  = idx & ((L / 16) - 1);       // 0..255
    const int c   = (idx >> 8) & (C - 1);
    const int b   = idx >> 11;
    const int l0  = lv * 4;                     // chunk k at l0 + k*(L/4)

    const float mean = g_mean;
    const float inv  = g_inv;
    const float ga   = bn_gamma[0];
    const float be   = bn_beta[0];

    const float* inp = in + ((long long)b * L) * C + c;

    float d[4][4];
    #pragma unroll
    for (int k = 0; k < 4; ++k) {
        #pragma unroll
        for (int j = 0; j < 4; ++j) {
            int l = l0 + k * (L / 4) + j;
            float delta = (l == 0) ? 0.0f : (inp[l * C] - inp[(l - 1) * C]);
            float x = (delta - mean) * inv;
            d[k][j] = x * ga + be;
        }
    }

    float v[4][4];
    #pragma unroll
    for (int k = 0; k < 4; ++k)
        #pragma unroll
        for (int j = 0; j < 4; ++j) v[k][j] = 0.0f;

    float* op0 = out + (((long long)b * T) * C + c) * L + l0;

    #pragma unroll 4
    for (int t = 0; t < T; ++t) {
        const float w  = sw[t];
        const float bb = sb[t];
        const long long off = (long long)t * (C * L);

        float4 s4[4];
        #pragma unroll
        for (int k = 0; k < 4; ++k) {
            float x, *sp = &s4[k].x;
            #pragma unroll
            for (int j = 0; j < 4; ++j) {
                x = fmaf(d[k][j], w, bb);
                v[k][j] = v[k][j] + (x - v[k][j]) * 0.5f;
                bool p = (v[k][j] >= 1.0f);
                sp[j] = p ? 1.0f : 0.0f;
                v[k][j] = p ? 0.0f : v[k][j];
            }
        }
        #pragma unroll
        for (int k = 0; k < 4; ++k)
            __stcs(reinterpret_cast<float4*>(op0 + off + k * (L / 4)), s4[k]);
    }
}

// ---------------------------------------------------------------------------
extern "C" void kernel_launch(void* const* d_in, const int* in_sizes, int n_in,
                              void* d_out, int out_size)
{
    const float* in       = (const float*)d_in[0];
    const float* bn_gamma = (const float*)d_in[1];
    const float* bn_beta  = (const float*)d_in[2];
    const float* enc_w    = (const float*)d_in[3];
    const float* enc_b    = (const float*)d_in[4];
    float* out            = (float*)d_out;

    reduce_kernel<<<RED_BLOCKS, RED_THREADS>>>(in);

    const int total_thr = B * C * (L / 16);     // 65536
    lif_kernel<<<total_thr / 64, 64>>>(in, enc_w, enc_b, bn_gamma, bn_beta, out);
}